// round 9
// baseline (speedup 1.0000x reference)
#include <cuda_runtime.h>
#include <cuda_bf16.h>
#include <cstdint>
#include <cstddef>

#define NN 50000
#define NE 1600000
#define HID 64

// ---------------- device scratch (no runtime allocation allowed) ----------------
__device__ float g_insum[(size_t)NN * HID];
__device__ float g_A[(size_t)NN * HID];
__device__ float g_B[(size_t)NN * HID];
__device__ float g_nodemsg[(size_t)NN * HID];

// ---------------- packed fp32x2 helpers ----------------
__device__ __forceinline__ uint64_t splat2(float x) {
    uint64_t r;
    asm("mov.b64 %0, {%1, %1};" : "=l"(r) : "f"(x));
    return r;
}
__device__ __forceinline__ void fma2(uint64_t& d, uint64_t a, uint64_t b) {
    asm("fma.rn.f32x2 %0, %1, %2, %0;" : "+l"(d) : "l"(a), "l"(b));
}
__device__ __forceinline__ float2 unpk2(uint64_t v) {
    float2 f;
    asm("mov.b64 {%0, %1}, %2;" : "=f"(f.x), "=f"(f.y) : "l"(v));
    return f;
}
// vector float4 global reduction (sm_90+)
__device__ __forceinline__ void red4(float* p, float4 v) {
    asm volatile("red.global.add.v4.f32 [%0], {%1, %2, %3, %4};"
                 :: "l"(p), "f"(v.x), "f"(v.y), "f"(v.z), "f"(v.w) : "memory");
}

// ---------------- zero accumulators (every call; graph-replay safe) ----------------
__global__ void k_zero_accs() {
    size_t i = ((size_t)blockIdx.x * blockDim.x + threadIdx.x) * 4;
    if (i < (size_t)NN * HID) {
        *(float4*)(g_insum + i) = make_float4(0.f, 0.f, 0.f, 0.f);
        *(float4*)(g_nodemsg + i) = make_float4(0.f, 0.f, 0.f, 0.f);
    }
}

// ---------------- in_sum[r] += eh[e] via vector reduction, streaming ----------------
__global__ void __launch_bounds__(256) k_insum_red(const float* __restrict__ eh,
                                                   const int* __restrict__ ei) {
    size_t gid = (size_t)blockIdx.x * blockDim.x + threadIdx.x;
    if (gid >= (size_t)NE * 16) return;
    int e = (int)(gid >> 4);
    int q = (int)(gid & 15);
    int r = __ldg(ei + e);
    float4 v = *(const float4*)(eh + (size_t)e * HID + q * 4);
    red4(g_insum + (size_t)r * HID + q * 4, v);
}

// ---------------- small node GEMMs: A = x@W1^T, B = insum@W2^T + b ----------------
__global__ void __launch_bounds__(128) k_AB(const float* __restrict__ x,
                                            const float* __restrict__ Wm,
                                            const float* __restrict__ bm) {
    __shared__ float s_in[64][68];
    __shared__ float s_W[64][68];
    const int t = threadIdx.x;
    const int base = blockIdx.x * 64;
    const int e0 = (t & 15) * 4;
    const int o0 = (t >> 4) * 8;

    for (int pass = 0; pass < 2; pass++) {
        const int koff = pass * 64;
        for (int idx = t; idx < 4096; idx += 128) {
            int k = idx & 63, o = idx >> 6;
            s_W[k][o] = Wm[o * 128 + koff + k];
        }
        const float* src = (pass == 0) ? x : g_insum;
        for (int fi = t; fi < 1024; fi += 128) {
            int nl = fi >> 4, kq = fi & 15;
            int n = base + nl;
            float4 v = make_float4(0.f, 0.f, 0.f, 0.f);
            if (n < NN) v = *(const float4*)&src[(size_t)n * HID + kq * 4];
            s_in[kq * 4 + 0][nl] = v.x;
            s_in[kq * 4 + 1][nl] = v.y;
            s_in[kq * 4 + 2][nl] = v.z;
            s_in[kq * 4 + 3][nl] = v.w;
        }
        __syncthreads();

        uint64_t acc2[4][4];
#pragma unroll
        for (int i = 0; i < 4; i++)
#pragma unroll
            for (int j = 0; j < 4; j++) acc2[i][j] = 0ULL;

#pragma unroll 4
        for (int k = 0; k < 64; k++) {
            float4 a = *(float4*)&s_in[k][e0];
            const uint64_t* bp = (const uint64_t*)&s_W[k][o0];
            uint64_t b0 = bp[0], b1 = bp[1], b2 = bp[2], b3 = bp[3];
            uint64_t s0 = splat2(a.x), s1 = splat2(a.y), s2 = splat2(a.z), s3 = splat2(a.w);
            fma2(acc2[0][0], s0, b0); fma2(acc2[0][1], s0, b1); fma2(acc2[0][2], s0, b2); fma2(acc2[0][3], s0, b3);
            fma2(acc2[1][0], s1, b0); fma2(acc2[1][1], s1, b1); fma2(acc2[1][2], s1, b2); fma2(acc2[1][3], s1, b3);
            fma2(acc2[2][0], s2, b0); fma2(acc2[2][1], s2, b1); fma2(acc2[2][2], s2, b2); fma2(acc2[2][3], s2, b3);
            fma2(acc2[3][0], s3, b0); fma2(acc2[3][1], s3, b1); fma2(acc2[3][2], s3, b2); fma2(acc2[3][3], s3, b3);
        }

        float bb[8];
        if (pass == 1) {
#pragma unroll
            for (int j = 0; j < 8; j++) bb[j] = bm[o0 + j];
        } else {
#pragma unroll
            for (int j = 0; j < 8; j++) bb[j] = 0.f;
        }
        float* dst = (pass == 0) ? g_A : g_B;
#pragma unroll
        for (int i = 0; i < 4; i++) {
            int n = base + e0 + i;
            if (n < NN) {
                float2 p0 = unpk2(acc2[i][0]);
                float2 p1 = unpk2(acc2[i][1]);
                float2 p2 = unpk2(acc2[i][2]);
                float2 p3 = unpk2(acc2[i][3]);
                float4 r0 = make_float4(p0.x + bb[0], p0.y + bb[1], p1.x + bb[2], p1.y + bb[3]);
                float4 r1 = make_float4(p2.x + bb[4], p2.y + bb[5], p3.x + bb[6], p3.y + bb[7]);
                *(float4*)&dst[(size_t)n * HID + o0] = r0;
                *(float4*)&dst[(size_t)n * HID + o0 + 4] = r1;
            }
        }
        __syncthreads();
    }
}

// ---------------- heavy kernel: Q = eh@W2^T, msg = relu(A[row]+B[col]-Q[rev]),
//                  fused node_msg scatter via red.v4 ----------------
// NOTE: strides MUST be multiples of 4 floats (16B) for the float4/uint64 smem reads.
#define SEH 132
#define SW 68
#define MSG_SMEM_BYTES ((64 * SEH + 64 * SW) * 4 + 256 * 4)

__global__ void __launch_bounds__(256) k_msg(const float* __restrict__ eh,
                                             const int* __restrict__ ei,
                                             const float* __restrict__ Wm,
                                             float* __restrict__ msg) {
    extern __shared__ float sm[];
    float* s_eh = sm;                       // [64][SEH]
    float* s_W = sm + 64 * SEH;             // [64][SW]
    int* s_row = (int*)(sm + 64 * SEH + 64 * SW);
    int* s_col = s_row + 128;
    const int t = threadIdx.x;
    const int base = blockIdx.x * 128;

    for (int idx = t; idx < 4096; idx += 256) {
        int k = idx & 63, o = idx >> 6;
        s_W[k * SW + o] = Wm[o * 128 + 64 + k];
    }
    for (int fi = t; fi < 2048; fi += 256) {
        int el = fi >> 4, kq = fi & 15;
        float4 v = *(const float4*)&eh[(size_t)(base + el) * HID + kq * 4];
        s_eh[(kq * 4 + 0) * SEH + el] = v.x;
        s_eh[(kq * 4 + 1) * SEH + el] = v.y;
        s_eh[(kq * 4 + 2) * SEH + el] = v.z;
        s_eh[(kq * 4 + 3) * SEH + el] = v.w;
    }
    if (t < 128) {
        s_row[t] = ei[base + t];
        s_col[t] = ei[NE + base + t];
    }
    __syncthreads();

    const int e0 = (t & 31) * 4;   // 0..124, multiple of 4 -> reverse pairs in-thread
    const int o0 = (t >> 5) * 8;   // warp-uniform -> s_W broadcast reads
    uint64_t acc2[4][4];
#pragma unroll
    for (int i = 0; i < 4; i++)
#pragma unroll
        for (int j = 0; j < 4; j++) acc2[i][j] = 0ULL;

#pragma unroll 4
    for (int k = 0; k < 64; k++) {
        float4 a = *(float4*)&s_eh[k * SEH + e0];
        const uint64_t* bp = (const uint64_t*)&s_W[k * SW + o0];
        uint64_t b0 = bp[0], b1 = bp[1], b2 = bp[2], b3 = bp[3];
        uint64_t s0 = splat2(a.x), s1 = splat2(a.y), s2 = splat2(a.z), s3 = splat2(a.w);
        fma2(acc2[0][0], s0, b0); fma2(acc2[0][1], s0, b1); fma2(acc2[0][2], s0, b2); fma2(acc2[0][3], s0, b3);
        fma2(acc2[1][0], s1, b0); fma2(acc2[1][1], s1, b1); fma2(acc2[1][2], s1, b2); fma2(acc2[1][3], s1, b3);
        fma2(acc2[2][0], s2, b0); fma2(acc2[2][1], s2, b1); fma2(acc2[2][2], s2, b2); fma2(acc2[2][3], s2, b3);
        fma2(acc2[3][0], s3, b0); fma2(acc2[3][1], s3, b1); fma2(acc2[3][2], s3, b2); fma2(acc2[3][3], s3, b3);
    }

    // epilogue: edges e0..e0+3; Q of reverse of edge (e0+i) is acc row (i^1)
#pragma unroll
    for (int i = 0; i < 4; i++) {
        int el = e0 + i;
        size_t ge = (size_t)(base + el);
        int r = s_row[el];
        int c = s_col[el];
        const float* Ar = g_A + (size_t)r * HID + o0;
        const float* Bc = g_B + (size_t)c * HID + o0;
        float4 a0 = *(const float4*)Ar;
        float4 a1 = *(const float4*)(Ar + 4);
        float4 b0 = *(const float4*)Bc;
        float4 b1 = *(const float4*)(Bc + 4);
        int p = i ^ 1;
        float2 q0 = unpk2(acc2[p][0]);
        float2 q1 = unpk2(acc2[p][1]);
        float2 q2 = unpk2(acc2[p][2]);
        float2 q3 = unpk2(acc2[p][3]);
        float out[8];
        out[0] = a0.x + b0.x - q0.x;
        out[1] = a0.y + b0.y - q0.y;
        out[2] = a0.z + b0.z - q1.x;
        out[3] = a0.w + b0.w - q1.y;
        out[4] = a1.x + b1.x - q2.x;
        out[5] = a1.y + b1.y - q2.y;
        out[6] = a1.z + b1.z - q3.x;
        out[7] = a1.w + b1.w - q3.y;
#pragma unroll
        for (int j = 0; j < 8; j++) out[j] = out[j] > 0.f ? out[j] : 0.f;
        float4 m0 = make_float4(out[0], out[1], out[2], out[3]);
        float4 m1 = make_float4(out[4], out[5], out[6], out[7]);
        *(float4*)&msg[ge * HID + o0] = m0;
        *(float4*)&msg[ge * HID + o0 + 4] = m1;
        // fused node_msg scatter (L2-resident target)
        red4(g_nodemsg + (size_t)c * HID + o0, m0);
        red4(g_nodemsg + (size_t)c * HID + o0 + 4, m1);
    }
}

// ---------------- x_out = relu([x, node_msg] @ Wn^T + bn) ----------------
__global__ void __launch_bounds__(128) k_xout(const float* __restrict__ x,
                                              const float* __restrict__ Wn,
                                              const float* __restrict__ bn,
                                              float* __restrict__ xout) {
    __shared__ float s_in[64][68];
    __shared__ float s_W[64][68];
    const int t = threadIdx.x;
    const int base = blockIdx.x * 64;
    const int e0 = (t & 15) * 4;
    const int o0 = (t >> 4) * 8;
    uint64_t acc2[4][4];
#pragma unroll
    for (int i = 0; i < 4; i++)
#pragma unroll
        for (int j = 0; j < 4; j++) acc2[i][j] = 0ULL;

    for (int pass = 0; pass < 2; pass++) {
        const int koff = pass * 64;
        for (int idx = t; idx < 4096; idx += 128) {
            int k = idx & 63, o = idx >> 6;
            s_W[k][o] = Wn[o * 128 + koff + k];
        }
        const float* src = (pass == 0) ? x : g_nodemsg;
        for (int fi = t; fi < 1024; fi += 128) {
            int nl = fi >> 4, kq = fi & 15;
            int n = base + nl;
            float4 v = make_float4(0.f, 0.f, 0.f, 0.f);
            if (n < NN) v = *(const float4*)&src[(size_t)n * HID + kq * 4];
            s_in[kq * 4 + 0][nl] = v.x;
            s_in[kq * 4 + 1][nl] = v.y;
            s_in[kq * 4 + 2][nl] = v.z;
            s_in[kq * 4 + 3][nl] = v.w;
        }
        __syncthreads();
#pragma unroll 4
        for (int k = 0; k < 64; k++) {
            float4 a = *(float4*)&s_in[k][e0];
            const uint64_t* bp = (const uint64_t*)&s_W[k][o0];
            uint64_t b0 = bp[0], b1 = bp[1], b2 = bp[2], b3 = bp[3];
            uint64_t s0 = splat2(a.x), s1 = splat2(a.y), s2 = splat2(a.z), s3 = splat2(a.w);
            fma2(acc2[0][0], s0, b0); fma2(acc2[0][1], s0, b1); fma2(acc2[0][2], s0, b2); fma2(acc2[0][3], s0, b3);
            fma2(acc2[1][0], s1, b0); fma2(acc2[1][1], s1, b1); fma2(acc2[1][2], s1, b2); fma2(acc2[1][3], s1, b3);
            fma2(acc2[2][0], s2, b0); fma2(acc2[2][1], s2, b1); fma2(acc2[2][2], s2, b2); fma2(acc2[2][3], s2, b3);
            fma2(acc2[3][0], s3, b0); fma2(acc2[3][1], s3, b1); fma2(acc2[3][2], s3, b2); fma2(acc2[3][3], s3, b3);
        }
        __syncthreads();
    }

    float bb[8];
#pragma unroll
    for (int j = 0; j < 8; j++) bb[j] = bn[o0 + j];
#pragma unroll
    for (int i = 0; i < 4; i++) {
        int n = base + e0 + i;
        if (n < NN) {
            float2 p0 = unpk2(acc2[i][0]);
            float2 p1 = unpk2(acc2[i][1]);
            float2 p2 = unpk2(acc2[i][2]);
            float2 p3 = unpk2(acc2[i][3]);
            float o[8] = {p0.x + bb[0], p0.y + bb[1], p1.x + bb[2], p1.y + bb[3],
                          p2.x + bb[4], p2.y + bb[5], p3.x + bb[6], p3.y + bb[7]};
#pragma unroll
            for (int j = 0; j < 8; j++) o[j] = o[j] > 0.f ? o[j] : 0.f;
            *(float4*)&xout[(size_t)n * HID + o0] = make_float4(o[0], o[1], o[2], o[3]);
            *(float4*)&xout[(size_t)n * HID + o0 + 4] = make_float4(o[4], o[5], o[6], o[7]);
        }
    }
}

// ---------------- launch ----------------
extern "C" void kernel_launch(void* const* d_in, const int* in_sizes, int n_in,
                              void* d_out, int out_size) {
    const float* x  = (const float*)d_in[0];
    const int*   ei = (const int*)d_in[1];
    const float* eh = (const float*)d_in[2];
    const float* Wm = (const float*)d_in[3];
    const float* bm = (const float*)d_in[4];
    const float* Wn = (const float*)d_in[5];
    const float* bn = (const float*)d_in[6];
    float* xout = (float*)d_out;
    float* msg  = (float*)d_out + (size_t)NN * HID;

    cudaFuncSetAttribute(k_msg, cudaFuncAttributeMaxDynamicSharedMemorySize, MSG_SMEM_BYTES);

    k_zero_accs<<<(NN * HID / 4 + 255) / 256, 256>>>();
    k_insum_red<<<(int)(((size_t)NE * 16 + 255) / 256), 256>>>(eh, ei);
    k_AB<<<(NN + 63) / 64, 128>>>(x, Wm, bm);
    k_msg<<<NE / 128, 256, MSG_SMEM_BYTES>>>(eh, ei, Wm, msg);
    k_xout<<<(NN + 63) / 64, 128>>>(x, Wn, bn, xout);
}

// round 10
// speedup vs baseline: 1.5387x; 1.5387x over previous
#include <cuda_runtime.h>
#include <cuda_bf16.h>
#include <cstdint>
#include <cstddef>

#define NN 50000
#define NE 1600000
#define HID 64

// ---------------- device scratch (no runtime allocation allowed) ----------------
__device__ float g_insum[(size_t)NN * HID];
__device__ float g_A[(size_t)NN * HID];
__device__ float g_B[(size_t)NN * HID];
__device__ float g_nodemsg[(size_t)NN * HID];

// ---------------- packed fp32x2 helpers ----------------
__device__ __forceinline__ uint64_t splat2(float x) {
    uint64_t r;
    asm("mov.b64 %0, {%1, %1};" : "=l"(r) : "f"(x));
    return r;
}
__device__ __forceinline__ void fma2(uint64_t& d, uint64_t a, uint64_t b) {
    asm("fma.rn.f32x2 %0, %1, %2, %0;" : "+l"(d) : "l"(a), "l"(b));
}
__device__ __forceinline__ float2 unpk2(uint64_t v) {
    float2 f;
    asm("mov.b64 {%0, %1}, %2;" : "=f"(f.x), "=f"(f.y) : "l"(v));
    return f;
}
// vector float4 global reduction (sm_90+)
__device__ __forceinline__ void red4(float* p, float4 v) {
    asm volatile("red.global.add.v4.f32 [%0], {%1, %2, %3, %4};"
                 :: "l"(p), "f"(v.x), "f"(v.y), "f"(v.z), "f"(v.w) : "memory");
}

// ---------------- zero accumulators (every call; graph-replay safe) ----------------
__global__ void k_zero_accs() {
    size_t i = ((size_t)blockIdx.x * blockDim.x + threadIdx.x) * 4;
    if (i < (size_t)NN * HID) {
        *(float4*)(g_insum + i) = make_float4(0.f, 0.f, 0.f, 0.f);
        *(float4*)(g_nodemsg + i) = make_float4(0.f, 0.f, 0.f, 0.f);
    }
}

// ---------------- in_sum[r] += eh[e] via vector reduction, streaming ----------------
__global__ void __launch_bounds__(256) k_insum_red(const float* __restrict__ eh,
                                                   const int* __restrict__ ei) {
    size_t gid = (size_t)blockIdx.x * blockDim.x + threadIdx.x;
    if (gid >= (size_t)NE * 16) return;
    int e = (int)(gid >> 4);
    int q = (int)(gid & 15);
    int r = __ldg(ei + e);
    float4 v = *(const float4*)(eh + (size_t)e * HID + q * 4);
    red4(g_insum + (size_t)r * HID + q * 4, v);
}

// ---------------- small node GEMMs: A = x@W1^T, B = insum@W2^T + b ----------------
__global__ void __launch_bounds__(128) k_AB(const float* __restrict__ x,
                                            const float* __restrict__ Wm,
                                            const float* __restrict__ bm) {
    __shared__ float s_in[64][68];
    __shared__ float s_W[64][68];
    const int t = threadIdx.x;
    const int base = blockIdx.x * 64;
    const int e0 = (t & 15) * 4;
    const int o0 = (t >> 4) * 8;

    for (int pass = 0; pass < 2; pass++) {
        const int koff = pass * 64;
        for (int idx = t; idx < 4096; idx += 128) {
            int k = idx & 63, o = idx >> 6;
            s_W[k][o] = Wm[o * 128 + koff + k];
        }
        const float* src = (pass == 0) ? x : g_insum;
        for (int fi = t; fi < 1024; fi += 128) {
            int nl = fi >> 4, kq = fi & 15;
            int n = base + nl;
            float4 v = make_float4(0.f, 0.f, 0.f, 0.f);
            if (n < NN) v = *(const float4*)&src[(size_t)n * HID + kq * 4];
            s_in[kq * 4 + 0][nl] = v.x;
            s_in[kq * 4 + 1][nl] = v.y;
            s_in[kq * 4 + 2][nl] = v.z;
            s_in[kq * 4 + 3][nl] = v.w;
        }
        __syncthreads();

        uint64_t acc2[4][4];
#pragma unroll
        for (int i = 0; i < 4; i++)
#pragma unroll
            for (int j = 0; j < 4; j++) acc2[i][j] = 0ULL;

#pragma unroll 4
        for (int k = 0; k < 64; k++) {
            float4 a = *(float4*)&s_in[k][e0];
            const uint64_t* bp = (const uint64_t*)&s_W[k][o0];
            uint64_t b0 = bp[0], b1 = bp[1], b2 = bp[2], b3 = bp[3];
            uint64_t s0 = splat2(a.x), s1 = splat2(a.y), s2 = splat2(a.z), s3 = splat2(a.w);
            fma2(acc2[0][0], s0, b0); fma2(acc2[0][1], s0, b1); fma2(acc2[0][2], s0, b2); fma2(acc2[0][3], s0, b3);
            fma2(acc2[1][0], s1, b0); fma2(acc2[1][1], s1, b1); fma2(acc2[1][2], s1, b2); fma2(acc2[1][3], s1, b3);
            fma2(acc2[2][0], s2, b0); fma2(acc2[2][1], s2, b1); fma2(acc2[2][2], s2, b2); fma2(acc2[2][3], s2, b3);
            fma2(acc2[3][0], s3, b0); fma2(acc2[3][1], s3, b1); fma2(acc2[3][2], s3, b2); fma2(acc2[3][3], s3, b3);
        }

        float bb[8];
        if (pass == 1) {
#pragma unroll
            for (int j = 0; j < 8; j++) bb[j] = bm[o0 + j];
        } else {
#pragma unroll
            for (int j = 0; j < 8; j++) bb[j] = 0.f;
        }
        float* dst = (pass == 0) ? g_A : g_B;
#pragma unroll
        for (int i = 0; i < 4; i++) {
            int n = base + e0 + i;
            if (n < NN) {
                float2 p0 = unpk2(acc2[i][0]);
                float2 p1 = unpk2(acc2[i][1]);
                float2 p2 = unpk2(acc2[i][2]);
                float2 p3 = unpk2(acc2[i][3]);
                float4 r0 = make_float4(p0.x + bb[0], p0.y + bb[1], p1.x + bb[2], p1.y + bb[3]);
                float4 r1 = make_float4(p2.x + bb[4], p2.y + bb[5], p3.x + bb[6], p3.y + bb[7]);
                *(float4*)&dst[(size_t)n * HID + o0] = r0;
                *(float4*)&dst[(size_t)n * HID + o0 + 4] = r1;
            }
        }
        __syncthreads();
    }
}

// ---------------- heavy kernel ----------------
// Q = eh@W2^T (fp32x2 FMA), staged to swizzled smem, then fully-coalesced epilogue:
// half-warp = one edge, lanes = 16B chunks. msg = relu(A[row]+B[col]-Q[e^1]),
// fused node_msg scatter via red.v4.
#define SEH 130                    // s_eh stride (floats), even -> 8B-aligned float2 reads
#define SW 68                      // s_W stride (floats), mult of 4 -> LDS.128
#define EH_FLOATS (64 * SEH)       // 8320 floats = 33280 B (stage aliases first 32768 B)
#define W_FLOATS (64 * SW)         // 4352 floats
#define MSG_SMEM_BYTES ((EH_FLOATS + W_FLOATS) * 4 + 256 * 4)

__global__ void __launch_bounds__(256) k_msg(const float* __restrict__ eh,
                                             const int* __restrict__ ei,
                                             const float* __restrict__ Wm,
                                             float* __restrict__ msg) {
    extern __shared__ float sm[];
    float* s_eh = sm;                             // [64][SEH]
    float* s_W = sm + EH_FLOATS;                  // [64][SW]
    int* s_row = (int*)(sm + EH_FLOATS + W_FLOATS);
    int* s_col = s_row + 128;
    float4* stage4 = (float4*)sm;                 // aliases s_eh: 128 edges x 16 groups, swizzled
    const int t = threadIdx.x;
    const int base = blockIdx.x * 128;

    // ---- fills ----
    for (int idx = t; idx < 4096; idx += 256) {
        int k = idx & 63, o = idx >> 6;
        s_W[k * SW + o] = Wm[o * 128 + 64 + k];
    }
    for (int fi = t; fi < 2048; fi += 256) {
        int el = fi >> 4, kq = fi & 15;
        float4 v = *(const float4*)&eh[(size_t)(base + el) * HID + kq * 4];
        s_eh[(kq * 4 + 0) * SEH + el] = v.x;
        s_eh[(kq * 4 + 1) * SEH + el] = v.y;
        s_eh[(kq * 4 + 2) * SEH + el] = v.z;
        s_eh[(kq * 4 + 3) * SEH + el] = v.w;
    }
    if (t < 128) {
        s_row[t] = ei[base + t];
        s_col[t] = ei[NE + base + t];
    }
    __syncthreads();

    // ---- mainloop: thread tile 4 edges (e0..e0+3) x 8 outs (o0..o0+7) ----
    const int e0 = (t & 31) * 4;
    const int o0 = (t >> 5) * 8;
    uint64_t acc2[4][4];
#pragma unroll
    for (int i = 0; i < 4; i++)
#pragma unroll
        for (int j = 0; j < 4; j++) acc2[i][j] = 0ULL;

#pragma unroll 4
    for (int k = 0; k < 64; k++) {
        const float2* pa = (const float2*)&s_eh[k * SEH + e0];
        float2 a01 = pa[0], a23 = pa[1];
        ulonglong2 W01 = *(const ulonglong2*)&s_W[k * SW + o0];
        ulonglong2 W23 = *(const ulonglong2*)&s_W[k * SW + o0 + 4];
        uint64_t b0 = W01.x, b1 = W01.y, b2 = W23.x, b3 = W23.y;
        uint64_t s0 = splat2(a01.x), s1 = splat2(a01.y), s2 = splat2(a23.x), s3 = splat2(a23.y);
        fma2(acc2[0][0], s0, b0); fma2(acc2[0][1], s0, b1); fma2(acc2[0][2], s0, b2); fma2(acc2[0][3], s0, b3);
        fma2(acc2[1][0], s1, b0); fma2(acc2[1][1], s1, b1); fma2(acc2[1][2], s1, b2); fma2(acc2[1][3], s1, b3);
        fma2(acc2[2][0], s2, b0); fma2(acc2[2][1], s2, b1); fma2(acc2[2][2], s2, b2); fma2(acc2[2][3], s2, b3);
        fma2(acc2[3][0], s3, b0); fma2(acc2[3][1], s3, b1); fma2(acc2[3][2], s3, b2); fma2(acc2[3][3], s3, b3);
    }
    __syncthreads();  // mainloop reads of s_eh done; stage overwrites it

    // ---- stage Q: row-major 128x16 float4, XOR-swizzled group = g ^ (edge>>2) ----
    {
        const int g0 = o0 >> 2;
#pragma unroll
        for (int i = 0; i < 4; i++) {
            int el = e0 + i;
            int j = el >> 2;  // = t & 31
            float2 p0 = unpk2(acc2[i][0]);
            float2 p1 = unpk2(acc2[i][1]);
            float2 p2 = unpk2(acc2[i][2]);
            float2 p3 = unpk2(acc2[i][3]);
            stage4[el * 16 + ((g0 ^ j) & 15)] = make_float4(p0.x, p0.y, p1.x, p1.y);
            stage4[el * 16 + (((g0 + 1) ^ j) & 15)] = make_float4(p2.x, p2.y, p3.x, p3.y);
        }
    }
    __syncthreads();

    // ---- coalesced epilogue: half-warp = edge, lanes = 16B chunks ----
    {
        const int wd = t >> 5;
        const int lane = t & 31;
        const int c4 = lane & 15;
        const int hw = lane >> 4;
#pragma unroll
        for (int p = 0; p < 8; p++) {
            int eb = p * 16 + wd * 2 + hw;          // tile-local edge
            int er = eb ^ 1;                        // its reverse (same tile)
            float4 q = stage4[er * 16 + ((c4 ^ (er >> 2)) & 15)];
            int r = s_row[eb];
            int c = s_col[eb];
            float4 a = *(const float4*)(g_A + (size_t)r * HID + c4 * 4);
            float4 b = *(const float4*)(g_B + (size_t)c * HID + c4 * 4);
            float4 o;
            o.x = a.x + b.x - q.x;
            o.y = a.y + b.y - q.y;
            o.z = a.z + b.z - q.z;
            o.w = a.w + b.w - q.w;
            o.x = o.x > 0.f ? o.x : 0.f;
            o.y = o.y > 0.f ? o.y : 0.f;
            o.z = o.z > 0.f ? o.z : 0.f;
            o.w = o.w > 0.f ? o.w : 0.f;
            *(float4*)(msg + (size_t)(base + eb) * HID + c4 * 4) = o;
            red4(g_nodemsg + (size_t)c * HID + c4 * 4, o);
        }
    }
}

// ---------------- x_out = relu([x, node_msg] @ Wn^T + bn) ----------------
__global__ void __launch_bounds__(128) k_xout(const float* __restrict__ x,
                                              const float* __restrict__ Wn,
                                              const float* __restrict__ bn,
                                              float* __restrict__ xout) {
    __shared__ float s_in[64][68];
    __shared__ float s_W[64][68];
    const int t = threadIdx.x;
    const int base = blockIdx.x * 64;
    const int e0 = (t & 15) * 4;
    const int o0 = (t >> 4) * 8;
    uint64_t acc2[4][4];
#pragma unroll
    for (int i = 0; i < 4; i++)
#pragma unroll
        for (int j = 0; j < 4; j++) acc2[i][j] = 0ULL;

    for (int pass = 0; pass < 2; pass++) {
        const int koff = pass * 64;
        for (int idx = t; idx < 4096; idx += 128) {
            int k = idx & 63, o = idx >> 6;
            s_W[k][o] = Wn[o * 128 + koff + k];
        }
        const float* src = (pass == 0) ? x : g_nodemsg;
        for (int fi = t; fi < 1024; fi += 128) {
            int nl = fi >> 4, kq = fi & 15;
            int n = base + nl;
            float4 v = make_float4(0.f, 0.f, 0.f, 0.f);
            if (n < NN) v = *(const float4*)&src[(size_t)n * HID + kq * 4];
            s_in[kq * 4 + 0][nl] = v.x;
            s_in[kq * 4 + 1][nl] = v.y;
            s_in[kq * 4 + 2][nl] = v.z;
            s_in[kq * 4 + 3][nl] = v.w;
        }
        __syncthreads();
#pragma unroll 4
        for (int k = 0; k < 64; k++) {
            float4 a = *(float4*)&s_in[k][e0];
            const uint64_t* bp = (const uint64_t*)&s_W[k][o0];
            uint64_t b0 = bp[0], b1 = bp[1], b2 = bp[2], b3 = bp[3];
            uint64_t s0 = splat2(a.x), s1 = splat2(a.y), s2 = splat2(a.z), s3 = splat2(a.w);
            fma2(acc2[0][0], s0, b0); fma2(acc2[0][1], s0, b1); fma2(acc2[0][2], s0, b2); fma2(acc2[0][3], s0, b3);
            fma2(acc2[1][0], s1, b0); fma2(acc2[1][1], s1, b1); fma2(acc2[1][2], s1, b2); fma2(acc2[1][3], s1, b3);
            fma2(acc2[2][0], s2, b0); fma2(acc2[2][1], s2, b1); fma2(acc2[2][2], s2, b2); fma2(acc2[2][3], s2, b3);
            fma2(acc2[3][0], s3, b0); fma2(acc2[3][1], s3, b1); fma2(acc2[3][2], s3, b2); fma2(acc2[3][3], s3, b3);
        }
        __syncthreads();
    }

    float bb[8];
#pragma unroll
    for (int j = 0; j < 8; j++) bb[j] = bn[o0 + j];
#pragma unroll
    for (int i = 0; i < 4; i++) {
        int n = base + e0 + i;
        if (n < NN) {
            float2 p0 = unpk2(acc2[i][0]);
            float2 p1 = unpk2(acc2[i][1]);
            float2 p2 = unpk2(acc2[i][2]);
            float2 p3 = unpk2(acc2[i][3]);
            float o[8] = {p0.x + bb[0], p0.y + bb[1], p1.x + bb[2], p1.y + bb[3],
                          p2.x + bb[4], p2.y + bb[5], p3.x + bb[6], p3.y + bb[7]};
#pragma unroll
            for (int j = 0; j < 8; j++) o[j] = o[j] > 0.f ? o[j] : 0.f;
            *(float4*)&xout[(size_t)n * HID + o0] = make_float4(o[0], o[1], o[2], o[3]);
            *(float4*)&xout[(size_t)n * HID + o0 + 4] = make_float4(o[4], o[5], o[6], o[7]);
        }
    }
}

// ---------------- launch ----------------
extern "C" void kernel_launch(void* const* d_in, const int* in_sizes, int n_in,
                              void* d_out, int out_size) {
    const float* x  = (const float*)d_in[0];
    const int*   ei = (const int*)d_in[1];
    const float* eh = (const float*)d_in[2];
    const float* Wm = (const float*)d_in[3];
    const float* bm = (const float*)d_in[4];
    const float* Wn = (const float*)d_in[5];
    const float* bn = (const float*)d_in[6];
    float* xout = (float*)d_out;
    float* msg  = (float*)d_out + (size_t)NN * HID;

    cudaFuncSetAttribute(k_msg, cudaFuncAttributeMaxDynamicSharedMemorySize, MSG_SMEM_BYTES);

    k_zero_accs<<<(NN * HID / 4 + 255) / 256, 256>>>();
    k_insum_red<<<(int)(((size_t)NE * 16 + 255) / 256), 256>>>(eh, ei);
    k_AB<<<(NN + 63) / 64, 128>>>(x, Wm, bm);
    k_msg<<<NE / 128, 256, MSG_SMEM_BYTES>>>(eh, ei, Wm, msg);
    k_xout<<<(NN + 63) / 64, 128>>>(x, Wn, bn, xout);
}